// round 4
// baseline (speedup 1.0000x reference)
#include <cuda_runtime.h>
#include <math.h>

#define EPS 1e-4f

#define B_  2048
#define H1_ 23
#define W1_ 31
#define H2_ 11
#define W2_ 15
#define H3_ 5
#define W3_ 7

#define S1 (B_*H1_*W1_)          // 1,460,224 sites @23x31
#define S2 (B_*H2_*W2_)          // 337,920 sites @11x15
#define S3 (B_*H3_*W3_)          // 71,680 sites @5x7

// ---------------- scratch (device globals; no allocations) ----------------
__device__ float g_xm[S1*2];
__device__ float g_m1[S1];
__device__ float g_h1[S1*16];
__device__ float g_h2[S1*32];
__device__ float g_p1[S2*32];
__device__ float g_m2[S2];
__device__ float g_h3[S2*64];
__device__ float g_h4[S2*128];
__device__ float g_p2[S3*128];
__device__ float g_m3[S3];
__device__ float g_gates[S3*768];     // i | o | g (f-gate skipped)
__device__ float g_flat[B_*8960];
__device__ float g_y1[B_*1024];
__device__ float g_stats[544];        // [0,512): per-layer sums/sqsums; [512],[513]: counts

// ---------------- small kernels ----------------
__global__ void k_zero_stats(float* st) {
    if (threadIdx.x < 544) st[threadIdx.x] = 0.f;
}

// xm = x*m, m1f = float(mask), count active -> nP
__global__ void k_prep(const float* __restrict__ x, const int* __restrict__ mask,
                       float* __restrict__ xm, float* __restrict__ m1, float* nP) {
    int s = blockIdx.x * blockDim.x + threadIdx.x;
    int act = 0;
    if (s < S1) {
        float m = (float)mask[s];
        m1[s] = m;
        xm[2*s]   = x[2*s]   * m;
        xm[2*s+1] = x[2*s+1] * m;
        act = (m > 0.f);
    }
    __shared__ int sh[256];
    sh[threadIdx.x] = act; __syncthreads();
    for (int o = 128; o > 0; o >>= 1) { if (threadIdx.x < o) sh[threadIdx.x] += sh[threadIdx.x+o]; __syncthreads(); }
    if (threadIdx.x == 0 && sh[0]) atomicAdd(nP, (float)sh[0]);
}

// per-channel sum/sumsq over active sites. one warp strides over sites.
__global__ void k_stats(const float* __restrict__ v, const float* __restrict__ mf,
                        int sites, int C, float* __restrict__ sumP, float* __restrict__ sqP) {
    int lane = threadIdx.x & 31;
    int warp = (blockIdx.x * blockDim.x + threadIdx.x) >> 5;
    int nwarps = (gridDim.x * blockDim.x) >> 5;
    float sum[4] = {0,0,0,0}, sq[4] = {0,0,0,0};
    for (int s = warp; s < sites; s += nwarps) {
        if (mf[s] > 0.f) {
            const float* row = v + (size_t)s * C;
            #pragma unroll 4
            for (int j = 0; j * 32 < C && j < 4; j++) {
                int c = lane + 32*j;
                if (c < C) { float xv = row[c]; sum[j] += xv; sq[j] += xv*xv; }
            }
        }
    }
    #pragma unroll 4
    for (int j = 0; j * 32 < C && j < 4; j++) {
        int c = lane + 32*j;
        if (c < C) { atomicAdd(&sumP[c], sum[j]); atomicAdd(&sqP[c], sq[j]); }
    }
}

// y = relu((v-mean)*rsqrt(var+EPS)*gamma + beta) * m, in place
__global__ void k_apply(float* __restrict__ v, const float* __restrict__ mf,
                        int sites, int Cshift,
                        const float* __restrict__ sumP, const float* __restrict__ sqP,
                        const float* __restrict__ nP,
                        const float* __restrict__ gamma, const float* __restrict__ beta) {
    int C = 1 << Cshift;
    __shared__ float sc[128], so[128];
    if (threadIdx.x < C) {
        float n = fmaxf(nP[0], 1.f);
        float mean = sumP[threadIdx.x] / n;
        float var  = sqP[threadIdx.x] / n - mean*mean;
        float rs   = rsqrtf(var + EPS) * gamma[threadIdx.x];
        sc[threadIdx.x] = rs;
        so[threadIdx.x] = beta[threadIdx.x] - mean * rs;
    }
    __syncthreads();
    int e = blockIdx.x * blockDim.x + threadIdx.x;
    if (e < sites << Cshift) {
        int c = e & (C-1);
        int s = e >> Cshift;
        v[e] = fmaxf(v[e]*sc[c] + so[c], 0.f) * mf[s];
    }
}

// 3x3 stride-2 VALID maxpool with mask semantics; optional active-count
__global__ void k_pool(const float* __restrict__ in, const float* __restrict__ mfin,
                       float* __restrict__ out, float* __restrict__ mfout,
                       int Hi, int Wi, int Ho, int Wo, int Cshift, float* cntP) {
    int C = 1 << Cshift;
    int e = blockIdx.x * blockDim.x + threadIdx.x;
    int total = B_ * Ho * Wo * C;
    int newact = 0;
    if (e < total) {
        int c = e & (C-1);
        int s = e >> Cshift;
        int b = s / (Ho*Wo); int r = s - b*(Ho*Wo);
        int y = r / Wo;      int xo = r - y*Wo;
        float best = -1e30f, mm = 0.f;
        #pragma unroll
        for (int dy = 0; dy < 3; dy++)
            #pragma unroll
            for (int dx = 0; dx < 3; dx++) {
                int si = (b*Hi + 2*y + dy) * Wi + 2*xo + dx;
                float m = mfin[si];
                mm = fmaxf(mm, m);
                float vv = (m > 0.f) ? in[(size_t)si * C + c] : -1e30f;
                best = fmaxf(best, vv);
            }
        out[e] = (mm > 0.f) ? best : 0.f;
        if (c == 0) { mfout[s] = mm; newact = (mm > 0.f); }
    }
    if (cntP) {
        __shared__ int sh[256];
        sh[threadIdx.x] = newact; __syncthreads();
        for (int o = 128; o > 0; o >>= 1) { if (threadIdx.x < o) sh[threadIdx.x] += sh[threadIdx.x+o]; __syncthreads(); }
        if (threadIdx.x == 0 && sh[0]) atomicAdd(cntP, (float)sh[0]);
    }
}

// ConvLSTM nonlinearity -> flat in (C,H,W) order
__global__ void k_lstm(const float* __restrict__ gates, const float* __restrict__ m3,
                       float* __restrict__ flat) {
    int e = blockIdx.x * blockDim.x + threadIdx.x;
    if (e >= S3 * 256) return;
    int c = e & 255;
    int s = e >> 8;
    const float* g = gates + (size_t)s * 768;
    float gi = g[c], go = g[256 + c], gg = g[512 + c];
    float si = 1.f / (1.f + __expf(-gi));
    float so = 1.f / (1.f + __expf(-go));
    float cc = si * tanhf(gg);
    float hh = so * tanhf(cc) * m3[s];
    int b = s / (H3_*W3_); int r = s - b*(H3_*W3_);
    flat[b*8960 + c*35 + r] = hh;
}

// ---------------- generic GEMM: C[M,N] = gather(A)[M,K] @ B[K,N] ----------------
// MODE 0: dense A row-major.  MODE 1: on-the-fly im2col (3x3 SAME, zero halo).
// EPI 0: raw. 1: +bias. 2: +bias, relu. 3: gate column remap (skip f) + bias.
struct GemmP {
    const float* A; const float* Bw; const float* bias; float* C;
    int M, N, K, ldb;
    const float* img; int IH, IW, IC;
};

template<int MODE, int EPI>
__global__ void __launch_bounds__(256) k_gemm(GemmP p) {
    __shared__ float As[16][65];
    __shared__ float Bs[16][68];
    int tx = threadIdx.x & 15, ty = threadIdx.x >> 4;
    int n0 = blockIdx.x * 64, m0 = blockIdx.y * 64;
    float acc[4][4] = {};

    for (int k0 = 0; k0 < p.K; k0 += 16) {
        #pragma unroll
        for (int i = 0; i < 4; i++) {
            int e = threadIdx.x + i*256;
            int ml = e >> 4, kl = e & 15;
            int m = m0 + ml, k = k0 + kl;
            float v = 0.f;
            if (m < p.M && k < p.K) {
                if (MODE == 0) {
                    v = p.A[(size_t)m * p.K + k];
                } else {
                    int hw = p.IH * p.IW;
                    int b = m / hw; int r = m - b*hw;
                    int y = r / p.IW; int x = r - y*p.IW;
                    int c = k % p.IC; int t9 = k / p.IC;
                    int ky = t9 / 3, kx = t9 - ky*3;
                    int yy = y + ky - 1, xx = x + kx - 1;
                    if (yy >= 0 && yy < p.IH && xx >= 0 && xx < p.IW)
                        v = p.img[(size_t)((b*p.IH + yy)*p.IW + xx) * p.IC + c];
                }
            }
            As[kl][ml] = v;
        }
        #pragma unroll
        for (int i = 0; i < 4; i++) {
            int e = threadIdx.x + i*256;
            int kl = e >> 6, nl = e & 63;
            int k = k0 + kl, n = n0 + nl;
            float v = 0.f;
            if (k < p.K && n < p.N) {
                int nn = (EPI == 3 && n >= 256) ? n + 256 : n;
                v = p.Bw[(size_t)k * p.ldb + nn];
            }
            Bs[kl][nl] = v;
        }
        __syncthreads();
        #pragma unroll
        for (int kk = 0; kk < 16; kk++) {
            float a[4], b[4];
            #pragma unroll
            for (int i = 0; i < 4; i++) a[i] = As[kk][ty*4 + i];
            #pragma unroll
            for (int j = 0; j < 4; j++) b[j] = Bs[kk][tx*4 + j];
            #pragma unroll
            for (int i = 0; i < 4; i++)
                #pragma unroll
                for (int j = 0; j < 4; j++)
                    acc[i][j] += a[i] * b[j];
        }
        __syncthreads();
    }

    #pragma unroll
    for (int i = 0; i < 4; i++) {
        int m = m0 + ty*4 + i;
        if (m >= p.M) continue;
        #pragma unroll
        for (int j = 0; j < 4; j++) {
            int n = n0 + tx*4 + j;
            if (n >= p.N) continue;
            float v = acc[i][j];
            if (EPI >= 1) {
                int nn = (EPI == 3 && n >= 256) ? n + 256 : n;
                v += p.bias[nn];
            }
            if (EPI == 2) v = fmaxf(v, 0.f);
            p.C[(size_t)m * p.N + n] = v;
        }
    }
}

// ---------------- launcher ----------------
static inline int ceil_div(int a, int b) { return (a + b - 1) / b; }

extern "C" void kernel_launch(void* const* d_in, const int* in_sizes, int n_in,
                              void* d_out, int out_size) {
    const float* x    = (const float*)d_in[0];
    const int*   mask = (const int*)  d_in[1];
    const float* W1 = (const float*)d_in[2];  const float* ga1 = (const float*)d_in[3];  const float* be1 = (const float*)d_in[4];
    const float* W2 = (const float*)d_in[5];  const float* ga2 = (const float*)d_in[6];  const float* be2 = (const float*)d_in[7];
    const float* W3 = (const float*)d_in[8];  const float* ga3 = (const float*)d_in[9];  const float* be3 = (const float*)d_in[10];
    const float* W4 = (const float*)d_in[11]; const float* ga4 = (const float*)d_in[12]; const float* be4 = (const float*)d_in[13];
    const float* Wl = (const float*)d_in[14]; const float* bl  = (const float*)d_in[15];
    const float* lw1 = (const float*)d_in[16]; const float* lb1 = (const float*)d_in[17];
    const float* lw2 = (const float*)d_in[18]; const float* lb2 = (const float*)d_in[19];
    float* out = (float*)d_out;

    float *xm, *m1, *h1, *h2, *p1, *m2, *h3, *h4, *p2, *m3, *gates, *flat, *y1, *st;
    cudaGetSymbolAddress((void**)&xm,    g_xm);
    cudaGetSymbolAddress((void**)&m1,    g_m1);
    cudaGetSymbolAddress((void**)&h1,    g_h1);
    cudaGetSymbolAddress((void**)&h2,    g_h2);
    cudaGetSymbolAddress((void**)&p1,    g_p1);
    cudaGetSymbolAddress((void**)&m2,    g_m2);
    cudaGetSymbolAddress((void**)&h3,    g_h3);
    cudaGetSymbolAddress((void**)&h4,    g_h4);
    cudaGetSymbolAddress((void**)&p2,    g_p2);
    cudaGetSymbolAddress((void**)&m3,    g_m3);
    cudaGetSymbolAddress((void**)&gates, g_gates);
    cudaGetSymbolAddress((void**)&flat,  g_flat);
    cudaGetSymbolAddress((void**)&y1,    g_y1);
    cudaGetSymbolAddress((void**)&st,    g_stats);

    // stats layout: sums/sqsums in [0,512); counts isolated at [512],[513]
    float *sum1 = st+0,   *sq1 = st+16;
    float *sum2 = st+32,  *sq2 = st+64;
    float *sum3 = st+128, *sq3 = st+192;
    float *sum4 = st+256, *sq4 = st+384;
    float *n1 = st+512, *n2 = st+513;

    k_zero_stats<<<1, 1024>>>(st);
    k_prep<<<ceil_div(S1, 256), 256>>>(x, mask, xm, m1, n1);

    // conv1: 2->16
    { GemmP p = { nullptr, W1, nullptr, h1, S1, 16, 18, 16, xm, H1_, W1_, 2 };
      k_gemm<1,0><<<dim3(1, S1/64), 256>>>(p); }
    k_stats<<<2048, 256>>>(h1, m1, S1, 16, sum1, sq1);
    k_apply<<<ceil_div(S1*16, 256), 256>>>(h1, m1, S1, 4, sum1, sq1, n1, ga1, be1);

    // conv2: 16->32
    { GemmP p = { nullptr, W2, nullptr, h2, S1, 32, 144, 32, h1, H1_, W1_, 16 };
      k_gemm<1,0><<<dim3(1, S1/64), 256>>>(p); }
    k_stats<<<2048, 256>>>(h2, m1, S1, 32, sum2, sq2);
    k_apply<<<ceil_div(S1*32, 256), 256>>>(h2, m1, S1, 5, sum2, sq2, n1, ga2, be2);

    // pool1 -> p1 [B,11,15,32], m2, count n2
    k_pool<<<ceil_div(S2*32, 256), 256>>>(h2, m1, p1, m2, H1_, W1_, H2_, W2_, 5, n2);

    // conv3: 32->64
    { GemmP p = { nullptr, W3, nullptr, h3, S2, 64, 288, 64, p1, H2_, W2_, 32 };
      k_gemm<1,0><<<dim3(1, S2/64), 256>>>(p); }
    k_stats<<<2048, 256>>>(h3, m2, S2, 64, sum3, sq3);
    k_apply<<<ceil_div(S2*64, 256), 256>>>(h3, m2, S2, 6, sum3, sq3, n2, ga3, be3);

    // conv4: 64->128
    { GemmP p = { nullptr, W4, nullptr, h4, S2, 128, 576, 128, h3, H2_, W2_, 64 };
      k_gemm<1,0><<<dim3(2, S2/64), 256>>>(p); }
    k_stats<<<2048, 256>>>(h4, m2, S2, 128, sum4, sq4);
    k_apply<<<ceil_div(S2*128, 256), 256>>>(h4, m2, S2, 7, sum4, sq4, n2, ga4, be4);

    // pool2 -> p2 [B,5,7,128], m3
    k_pool<<<ceil_div(S3*128, 256), 256>>>(h4, m2, p2, m3, H2_, W2_, H3_, W3_, 7, nullptr);

    // gate conv: 128->768 effective (i,o,g; f skipped via column remap), +bias
    { GemmP p = { nullptr, Wl, bl, gates, S3, 768, 1152, 1024, p2, H3_, W3_, 128 };
      k_gemm<1,3><<<dim3(12, S3/64), 256>>>(p); }

    // LSTM nonlinearity -> flat [B, 8960] in (C,H,W) order
    k_lstm<<<ceil_div(S3*256, 256), 256>>>(gates, m3, flat);

    // FC1: [2048,8960]x[8960,1024] + bias, relu
    { GemmP p = { flat, lw1, lb1, y1, B_, 1024, 8960, 1024, nullptr, 0, 0, 0 };
      k_gemm<0,2><<<dim3(16, 32), 256>>>(p); }

    // FC2: [2048,1024]x[1024,420] + bias -> out
    { GemmP p = { y1, lw2, lb2, out, B_, 420, 1024, 420, nullptr, 0, 0, 0 };
      k_gemm<0,1><<<dim3(7, 32), 256>>>(p); }
}